// round 1
// baseline (speedup 1.0000x reference)
#include <cuda_runtime.h>
#include <math.h>

// ---------------------------------------------------------------------------
// FraudNATHybridModel: CNN (conv1->pool->conv2->pool->mean) -> 4-wire quantum
// circuit -> BatchNorm(batch stats) -> Linear(4->1).
//
// Strategy:
//  K0: 1 block. Reproduce np.random.RandomState(12345) gate spec on-device
//      (MT19937 + legacy masked-rejection randint / Fisher-Yates permutation),
//      build U_post = (fixed gates) * (50 random ops) as a 16x16 complex matrix.
//  K1: 1 block per image (128 thr). Fused conv1+relu+maxpool (smem) ->
//      conv2+relu+maxpool+mean (smem) -> encoder product state -> psi = U*phi
//      -> Z expectations z[b][4].
//  K2: 1 block deterministic fp64 reduction: BN stats -> fold BN+FC into
//      coefficients.
//  K3: out[b] = c + sum_j a_j * z[b][j].
// ---------------------------------------------------------------------------

#define BMAX 8192

__device__ float2 g_U[256];          // U_post, row-major [i][j]
__device__ float  g_z[BMAX * 4];     // per-image Z expectations
__device__ float  g_coef[8];         // a[0..3], c

// ------------------------- complex helpers ---------------------------------
__device__ __forceinline__ float2 cmul(float2 a, float2 b) {
    return make_float2(a.x * b.x - a.y * b.y, a.x * b.y + a.y * b.x);
}
__device__ __forceinline__ float2 cadd(float2 a, float2 b) {
    return make_float2(a.x + b.x, a.y + b.y);
}
__device__ __forceinline__ float2 cfma_(float2 a, float2 b, float2 c) {
    c.x += a.x * b.x - a.y * b.y;
    c.y += a.x * b.y + a.y * b.x;
    return c;
}

// ------------------------- MT19937 (numpy legacy) --------------------------
__device__ unsigned mt_next(unsigned* mt, int* mti) {
    if (*mti >= 624) {
        for (int i = 0; i < 624; i++) {
            unsigned y = (mt[i] & 0x80000000u) | (mt[(i + 1) % 624] & 0x7fffffffu);
            unsigned v = mt[(i + 397) % 624] ^ (y >> 1);
            if (y & 1u) v ^= 0x9908b0dfu;
            mt[i] = v;
        }
        *mti = 0;
    }
    unsigned y = mt[(*mti)++];
    y ^= y >> 11;
    y ^= (y << 7) & 0x9d2c5680u;
    y ^= (y << 15) & 0xefc60000u;
    y ^= y >> 18;
    return y;
}

// apply 2x2 gate on wire w (wire w <-> bit (3-w)) to 16-amp state
__device__ void ap1(float2* s, int w, float2 u00, float2 u01, float2 u10, float2 u11) {
    int m = 8 >> w;
    for (int i = 0; i < 16; i++) {
        if (!(i & m)) {
            float2 a = s[i], b = s[i | m];
            s[i]     = cadd(cmul(u00, a), cmul(u01, b));
            s[i | m] = cadd(cmul(u10, a), cmul(u11, b));
        }
    }
}
// controlled 2x2 on target wt, control wc (applies when control bit = 1)
__device__ void ap2(float2* s, int wc, int wt, float2 u00, float2 u01, float2 u10, float2 u11) {
    int mc = 8 >> wc, mt2 = 8 >> wt;
    for (int i = 0; i < 16; i++) {
        if ((i & mc) && !(i & mt2)) {
            float2 a = s[i], b = s[i | mt2];
            s[i]       = cadd(cmul(u00, a), cmul(u01, b));
            s[i | mt2] = cadd(cmul(u10, a), cmul(u11, b));
        }
    }
}

// ------------------------- K0: build U_post --------------------------------
__global__ void k_setup(const float* __restrict__ gate_params,
                        const float* __restrict__ rand_params) {
    __shared__ unsigned smt[624];
    __shared__ int sg[50], sw0[50], sw1[50], sp[50];
    int tid = threadIdx.x;

    if (tid == 0) {
        // init_genrand(12345) — numpy legacy int seeding
        smt[0] = 12345u;
        for (int i = 1; i < 624; i++)
            smt[i] = 1812433253u * (smt[i - 1] ^ (smt[i - 1] >> 30)) + (unsigned)i;
        int mti = 624;
        int p = 0;
        for (int k = 0; k < 50; k++) {
            // randint(5): masked rejection, mask=7, max=4
            unsigned g;
            do { g = mt_next(smt, &mti) & 7u; } while (g > 4u);
            int w0, w1 = -1;
            if (g >= 3u) {
                // choice(4, size=2, replace=False) == permutation(4)[:2]
                int arr[4] = {0, 1, 2, 3};
                for (int i = 3; i >= 1; --i) {
                    unsigned mask = (unsigned)i;
                    mask |= mask >> 1; mask |= mask >> 2; mask |= mask >> 4;
                    unsigned j;
                    do { j = mt_next(smt, &mti) & mask; } while (j > (unsigned)i);
                    int t = arr[i]; arr[i] = arr[j]; arr[j] = t;
                }
                w0 = arr[0]; w1 = arr[1];
            } else {
                // randint(4): mask=3, max=3 (no rejection)
                w0 = (int)(mt_next(smt, &mti) & 3u);
            }
            sg[k] = (int)g; sw0[k] = w0; sw1[k] = w1;
            sp[k] = (g == 4u) ? -1 : p++;
        }
    }
    __syncthreads();

    if (tid < 16) {
        float2 st[16];
        for (int i = 0; i < 16; i++) st[i] = make_float2(i == tid ? 1.f : 0.f, 0.f);

        for (int k = 0; k < 50; k++) {
            int g = sg[k], w0 = sw0[k], w1 = sw1[k];
            float t = (sp[k] >= 0) ? rand_params[sp[k]] : 0.f;
            float sn, cs;
            sincosf(0.5f * t, &sn, &cs);
            if (g == 0) {         // rx
                ap1(st, w0, make_float2(cs, 0), make_float2(0, -sn),
                            make_float2(0, -sn), make_float2(cs, 0));
            } else if (g == 1) {  // ry
                ap1(st, w0, make_float2(cs, 0), make_float2(-sn, 0),
                            make_float2(sn, 0), make_float2(cs, 0));
            } else if (g == 2) {  // rz
                ap1(st, w0, make_float2(cs, -sn), make_float2(0, 0),
                            make_float2(0, 0), make_float2(cs, sn));
            } else if (g == 3) {  // crx
                ap2(st, w0, w1, make_float2(cs, 0), make_float2(0, -sn),
                                make_float2(0, -sn), make_float2(cs, 0));
            } else {              // cnot
                ap2(st, w0, w1, make_float2(0, 0), make_float2(1, 0),
                                make_float2(1, 0), make_float2(0, 0));
            }
        }
        // fixed trainable + fixed gates
        float sn, cs;
        sincosf(0.5f * gate_params[0], &sn, &cs);
        ap1(st, 0, make_float2(cs, 0), make_float2(0, -sn), make_float2(0, -sn), make_float2(cs, 0));
        sincosf(0.5f * gate_params[1], &sn, &cs);
        ap1(st, 1, make_float2(cs, 0), make_float2(-sn, 0), make_float2(sn, 0), make_float2(cs, 0));
        sincosf(0.5f * gate_params[2], &sn, &cs);
        ap1(st, 3, make_float2(cs, -sn), make_float2(0, 0), make_float2(0, 0), make_float2(cs, sn));
        sincosf(0.5f * gate_params[3], &sn, &cs);
        ap2(st, 0, 2, make_float2(cs, 0), make_float2(0, -sn), make_float2(0, -sn), make_float2(cs, 0));
        const float r = 0.70710678118654752f;
        ap1(st, 3, make_float2(r, 0), make_float2(r, 0), make_float2(r, 0), make_float2(-r, 0));
        ap1(st, 2, make_float2(0.5f, 0.5f), make_float2(0.5f, -0.5f),
                   make_float2(0.5f, -0.5f), make_float2(0.5f, 0.5f));
        ap2(st, 3, 0, make_float2(0, 0), make_float2(1, 0), make_float2(1, 0), make_float2(0, 0));

        for (int i = 0; i < 16; i++) g_U[i * 16 + tid] = st[i];
    }
}

// ------------------------- K1: fused per-image pipeline --------------------
__global__ __launch_bounds__(128) void k_main(const float* __restrict__ x,
                                              const float* __restrict__ w1,
                                              const float* __restrict__ b1,
                                              const float* __restrict__ w2,
                                              const float* __restrict__ b2) {
    __shared__ float sx[784];
    __shared__ float sw1c[72];
    __shared__ float sb1[8];
    __shared__ float sh1[8 * 196];       // conv1 pooled output [8][14][14]
    __shared__ float sw2c[1152];
    __shared__ float sb2[16];
    __shared__ float sc2[16 * 196];      // conv2 relu output [16][14][14]
    __shared__ float spool[16];
    __shared__ float2 sv[8];
    __shared__ float2 sphi[16];

    int tid = threadIdx.x;
    int b = blockIdx.x;
    const float* xb = x + (size_t)b * 784;

    for (int i = tid; i < 784; i += 128) sx[i] = xb[i];
    for (int i = tid; i < 72; i += 128) sw1c[i] = w1[i];
    if (tid < 8) sb1[tid] = b1[tid];
    for (int i = tid; i < 1152; i += 128) sw2c[i] = w2[i];
    if (tid < 16) sb2[tid] = b2[tid];
    __syncthreads();

    // ---- conv1 (1->8, 3x3 SAME) + relu + maxpool2 -> sh1 ----
    if (tid < 112) {
        int c = tid / 14, y = tid % 14;
        float om[14];
#pragma unroll
        for (int i = 0; i < 14; i++) om[i] = 0.f;   // relu >= 0
        float bias = sb1[c];
#pragma unroll
        for (int dy = 0; dy < 2; dy++) {
            int rrow = 2 * y + dy;
            float cr[28];
#pragma unroll
            for (int i = 0; i < 28; i++) cr[i] = bias;
#pragma unroll
            for (int ky = 0; ky < 3; ky++) {
                int iy = rrow + ky - 1;
                if (iy >= 0 && iy < 28) {
                    float rb[30];
                    rb[0] = 0.f; rb[29] = 0.f;
#pragma unroll
                    for (int i = 0; i < 28; i++) rb[i + 1] = sx[iy * 28 + i];
#pragma unroll
                    for (int kx = 0; kx < 3; kx++) {
                        float w = sw1c[c * 9 + ky * 3 + kx];
#pragma unroll
                        for (int i = 0; i < 28; i++) cr[i] += w * rb[i + kx];
                    }
                }
            }
#pragma unroll
            for (int i = 0; i < 14; i++)
                om[i] = fmaxf(om[i], fmaxf(cr[2 * i], cr[2 * i + 1]));
        }
#pragma unroll
        for (int i = 0; i < 14; i++) sh1[(c * 14 + y) * 14 + i] = om[i];
    }
    __syncthreads();

    // ---- conv2 (8->16, 3x3 SAME) + relu -> sc2 (2 out-channels / thread) ----
    if (tid < 112) {
        int cp = tid / 14, y = tid % 14;
        int c0 = 2 * cp, c1 = c0 + 1;
        float a0[14], a1[14];
        float bb0 = sb2[c0], bb1 = sb2[c1];
#pragma unroll
        for (int i = 0; i < 14; i++) { a0[i] = bb0; a1[i] = bb1; }
#pragma unroll
        for (int ic = 0; ic < 8; ic++) {
#pragma unroll
            for (int ky = 0; ky < 3; ky++) {
                int iy = y + ky - 1;
                if (iy >= 0 && iy < 14) {
                    float rb[16];
                    rb[0] = 0.f; rb[15] = 0.f;
#pragma unroll
                    for (int i = 0; i < 14; i++) rb[i + 1] = sh1[(ic * 14 + iy) * 14 + i];
#pragma unroll
                    for (int kx = 0; kx < 3; kx++) {
                        float w0v = sw2c[((c0 * 8 + ic) * 3 + ky) * 3 + kx];
                        float w1v = sw2c[((c1 * 8 + ic) * 3 + ky) * 3 + kx];
#pragma unroll
                        for (int i = 0; i < 14; i++) {
                            float v = rb[i + kx];
                            a0[i] += w0v * v;
                            a1[i] += w1v * v;
                        }
                    }
                }
            }
        }
#pragma unroll
        for (int i = 0; i < 14; i++) {
            sc2[(c0 * 14 + y) * 14 + i] = fmaxf(a0[i], 0.f);
            sc2[(c1 * 14 + y) * 14 + i] = fmaxf(a1[i], 0.f);
        }
    }
    __syncthreads();

    // ---- maxpool2 + spatial mean -> spool[16] (deterministic) ----
    {
        int wrp = tid >> 5, lane = tid & 31;
        for (int c = wrp * 4; c < wrp * 4 + 4; c++) {
            float sum = 0.f;
            for (int cell = lane; cell < 49; cell += 32) {
                int cy = cell / 7, cx = cell % 7;
                const float* base = &sc2[c * 196 + 2 * cy * 14 + 2 * cx];
                float m = fmaxf(fmaxf(base[0], base[1]), fmaxf(base[14], base[15]));
                sum += m;
            }
#pragma unroll
            for (int off = 16; off > 0; off >>= 1)
                sum += __shfl_xor_sync(0xffffffffu, sum, off);
            if (lane == 0) spool[c] = sum * (1.f / 49.f);
        }
    }
    __syncthreads();

    // ---- quantum: product-state encoder, psi = U_post * phi, Z expectations
    if (tid < 32) {
        int lane = tid;
        if (lane < 4) {
            float aa = spool[lane], bb = spool[4 + lane],
                  cc = spool[8 + lane], dd = spool[12 + lane];
            float sa, ca, sb, cb, sc, ccs, sd, cd;
            sincosf(0.5f * aa, &sa, &ca);
            sincosf(0.5f * bb, &sb, &cb);
            sincosf(0.5f * cc, &sc, &ccs);
            sincosf(0.5f * dd, &sd, &cd);
            // ry(a)|0>, then rz(b)
            float2 v0 = make_float2(ca * cb, -ca * sb);
            float2 v1 = make_float2(sa * cb, sa * sb);
            // rx(c):  v0' = c*v0 + (-i s)*v1 ; v1' = (-i s)*v0 + c*v1
            float2 t0 = make_float2(ccs * v0.x + sc * v1.y, ccs * v0.y - sc * v1.x);
            float2 t1 = make_float2(sc * v0.y + ccs * v1.x, -sc * v0.x + ccs * v1.y);
            // ry(d)
            float2 u0 = make_float2(cd * t0.x - sd * t1.x, cd * t0.y - sd * t1.y);
            float2 u1 = make_float2(sd * t0.x + cd * t1.x, sd * t0.y + cd * t1.y);
            sv[2 * lane] = u0;
            sv[2 * lane + 1] = u1;
        }
        __syncwarp();
        if (lane < 16) {
            float2 f0 = sv[0 + ((lane >> 3) & 1)];
            float2 f1 = sv[2 + ((lane >> 2) & 1)];
            float2 f2 = sv[4 + ((lane >> 1) & 1)];
            float2 f3 = sv[6 + (lane & 1)];
            sphi[lane] = cmul(cmul(f0, f1), cmul(f2, f3));
        }
        __syncwarp();
        float p = 0.f;
        if (lane < 16) {
            float2 psi = make_float2(0.f, 0.f);
#pragma unroll
            for (int j = 0; j < 16; j++) psi = cfma_(g_U[lane * 16 + j], sphi[j], psi);
            p = psi.x * psi.x + psi.y * psi.y;
        }
#pragma unroll
        for (int w = 0; w < 4; w++) {
            float sgn = ((lane >> (3 - w)) & 1) ? -p : p;
#pragma unroll
            for (int off = 16; off > 0; off >>= 1)
                sgn += __shfl_xor_sync(0xffffffffu, sgn, off);
            if (lane == 0) g_z[b * 4 + w] = sgn;
        }
    }
}

// ------------------------- K2: BN stats + fold into coefficients -----------
__global__ void k_reduce(const float* __restrict__ gam, const float* __restrict__ bet,
                         const float* __restrict__ fcw, const float* __restrict__ fcb,
                         int B) {
    __shared__ double red[256 * 8];
    int tid = threadIdx.x;
    double sm[4] = {0, 0, 0, 0}, sq[4] = {0, 0, 0, 0};
    for (int r = tid; r < B; r += 256) {
#pragma unroll
        for (int j = 0; j < 4; j++) {
            double v = (double)g_z[r * 4 + j];
            sm[j] += v;
            sq[j] += v * v;
        }
    }
#pragma unroll
    for (int j = 0; j < 4; j++) { red[tid * 8 + j] = sm[j]; red[tid * 8 + 4 + j] = sq[j]; }
    __syncthreads();
    for (int s = 128; s > 0; s >>= 1) {
        if (tid < s) {
#pragma unroll
            for (int j = 0; j < 8; j++) red[tid * 8 + j] += red[(tid + s) * 8 + j];
        }
        __syncthreads();
    }
    if (tid == 0) {
        double invB = 1.0 / (double)B;
        double csum = (double)fcb[0];
        for (int j = 0; j < 4; j++) {
            double mu = red[j] * invB;
            double var = red[4 + j] * invB - mu * mu;
            double sc = (double)gam[j] / sqrt(var + 1e-5);
            g_coef[j] = (float)((double)fcw[j] * sc);
            csum += (double)fcw[j] * ((double)bet[j] - mu * sc);
        }
        g_coef[4] = (float)csum;
    }
}

// ------------------------- K3: final output --------------------------------
__global__ void k_final(float* __restrict__ out, int B) {
    int b = blockIdx.x * blockDim.x + threadIdx.x;
    if (b < B) {
        out[b] = g_coef[4]
               + g_coef[0] * g_z[b * 4 + 0]
               + g_coef[1] * g_z[b * 4 + 1]
               + g_coef[2] * g_z[b * 4 + 2]
               + g_coef[3] * g_z[b * 4 + 3];
    }
}

extern "C" void kernel_launch(void* const* d_in, const int* in_sizes, int n_in,
                              void* d_out, int out_size) {
    const float* x   = (const float*)d_in[0];
    const float* c1w = (const float*)d_in[1];
    const float* c1b = (const float*)d_in[2];
    const float* c2w = (const float*)d_in[3];
    const float* c2b = (const float*)d_in[4];
    const float* gp  = (const float*)d_in[5];
    const float* rp  = (const float*)d_in[6];
    const float* gam = (const float*)d_in[7];
    const float* bet = (const float*)d_in[8];
    const float* fcw = (const float*)d_in[9];
    const float* fcb = (const float*)d_in[10];

    int B = in_sizes[0] / 784;
    if (B > BMAX) B = BMAX;

    k_setup<<<1, 32>>>(gp, rp);
    k_main<<<B, 128>>>(x, c1w, c1b, c2w, c2b);
    k_reduce<<<1, 256>>>(gam, bet, fcw, fcb, B);
    k_final<<<(B + 255) / 256, 256>>>((float*)d_out, B);
}